// round 1
// baseline (speedup 1.0000x reference)
#include <cuda_runtime.h>

#define BB   32
#define CIN  256
#define HH   56
#define WWD  56
#define COUT 256
#define NK   4
#define HID  64
#define TAPS 9
#define CITAP (CIN*TAPS)   // 2304

// -------- scratch (device globals; no allocation allowed) --------
__device__ float g_v[BB*CIN];
__device__ float g_a[BB*NK];
__device__ __align__(16) float g_wdyn[(size_t)BB*CITAP*COUT];   // [b][ci][tap][co] : 75.5 MB

// -------- f32x2 helpers (sm_100+ packed fp32 FMA: 2x FFMA rate) --------
__device__ __forceinline__ void ffma2(unsigned long long &d, unsigned long long a, unsigned long long b) {
    asm("fma.rn.f32x2 %0, %1, %2, %0;" : "+l"(d) : "l"(a), "l"(b));
}
__device__ __forceinline__ unsigned long long pack2(float lo, float hi) {
    unsigned long long r;
    asm("mov.b64 %0, {%1, %2};" : "=l"(r) : "f"(lo), "f"(hi));
    return r;
}
__device__ __forceinline__ unsigned long long dup2(float v) {
    unsigned long long r;
    asm("mov.b64 %0, {%1, %1};" : "=l"(r) : "f"(v));
    return r;
}
__device__ __forceinline__ void unpack2(unsigned long long v, float &lo, float &hi) {
    asm("mov.b64 {%0, %1}, %2;" : "=f"(lo), "=f"(hi) : "l"(v));
}

// ===================== 1) global average pool =====================
__global__ void gap_kernel(const float* __restrict__ x) {
    int bc = blockIdx.x;                       // b*CIN + c
    const float* p = x + (size_t)bc * (HH*WWD);
    float s = 0.f;
    for (int i = threadIdx.x; i < HH*WWD; i += 256) s += p[i];
    __shared__ float red[256];
    red[threadIdx.x] = s;
    __syncthreads();
    for (int off = 128; off > 0; off >>= 1) {
        if (threadIdx.x < off) red[threadIdx.x] += red[threadIdx.x + off];
        __syncthreads();
    }
    if (threadIdx.x == 0) g_v[bc] = red[0] * (1.0f / (HH*WWD));
}

// ===================== 2) router MLP + softmax =====================
__global__ void router_kernel(const float* __restrict__ fc1w, const float* __restrict__ fc1b,
                              const float* __restrict__ fc2w, const float* __restrict__ fc2b) {
    int b = blockIdx.x;
    __shared__ float sv[CIN];
    __shared__ float sh[HID];
    __shared__ float sl[NK];
    for (int i = threadIdx.x; i < CIN; i += 64) sv[i] = g_v[b*CIN + i];
    __syncthreads();
    int j = threadIdx.x;                        // 64 threads
    float acc = fc1b[j];
    for (int c = 0; c < CIN; c++) acc += sv[c] * fc1w[j*CIN + c];
    sh[j] = acc > 0.f ? acc : 0.f;
    __syncthreads();
    if (j < NK) {
        float l = fc2b[j];
        for (int t = 0; t < HID; t++) l += sh[t] * fc2w[j*HID + t];
        sl[j] = l;
    }
    __syncthreads();
    if (j == 0) {
        float m = sl[0];
        for (int k = 1; k < NK; k++) m = fmaxf(m, sl[k]);
        float e[NK], ssum = 0.f;
        for (int k = 0; k < NK; k++) { e[k] = expf(sl[k] - m); ssum += e[k]; }
        float inv = 1.0f / ssum;
        for (int k = 0; k < NK; k++) g_a[b*NK + k] = e[k] * inv;
    }
}

// ===================== 3) mix banks -> Wdyn[b][ci][tap][co] =====================
// smem-transposed so reads (bank: co-major) AND writes (wdyn: co contiguous) are coalesced.
__global__ void mix_kernel(const float* __restrict__ wb) {
    __shared__ float tile[32][289];            // [co_local][cit_local], pad 289 -> conflict-free transpose
    int b   = blockIdx.z;
    int co0 = blockIdx.y * 32;
    int ci0 = blockIdx.x * 32;
    int cit0 = ci0 * TAPS;                     // 288-wide contiguous chunk of (ci,tap)
    float a0 = g_a[b*NK+0], a1 = g_a[b*NK+1], a2 = g_a[b*NK+2], a3 = g_a[b*NK+3];
    const size_t BANK = (size_t)COUT * CITAP;  // 589824
    for (int idx = threadIdx.x; idx < 32*288; idx += 256) {
        int row = idx / 288;                   // co_local
        int c   = idx - row * 288;             // cit_local
        size_t base = (size_t)(co0 + row) * CITAP + cit0 + c;
        float v = a0*wb[base] + a1*wb[base + BANK] + a2*wb[base + 2*BANK] + a3*wb[base + 3*BANK];
        tile[row][c] = v;
    }
    __syncthreads();
    for (int idx = threadIdx.x; idx < 32*288; idx += 256) {
        int cit = idx >> 5;                    // 0..287
        int col = idx & 31;                    // co_local
        g_wdyn[((size_t)b*CITAP + cit0 + cit)*COUT + co0 + col] = tile[col][cit];
    }
}

// ===================== 4) conv: implicit GEMM on fma.rn.f32x2 =====================
// grid (28 row-pairs, 2 co-tiles, 32 samples); block 128 threads.
// Block tile: 128 cout x (2 rows x 56 cols). Thread tile: 8 cout x 14 px (7 f32x2 pairs).
#define KC 8
__global__ void __launch_bounds__(128, 2)
conv_kernel(const float* __restrict__ x, float* __restrict__ out) {
    __shared__ float sX[KC][4][64];                       // [kc][input row h0-1..h0+2][col+1, padded]
    __shared__ __align__(16) float sW[KC*TAPS*128];       // [(kc*9+tap)][co 0..127]

    int rp = blockIdx.x, ct = blockIdx.y, b = blockIdx.z;
    int tid  = threadIdx.x;
    int cog  = tid & 15;                 // 16 cout groups of 8
    int pg   = tid >> 4;                 // 8 pixel groups of 14
    int prow = pg >> 2;                  // 0..1
    int col0 = (pg & 3) * 14;            // 0,14,28,42
    int h0   = rp * 2;

    unsigned long long acc[8][7];
    #pragma unroll
    for (int i = 0; i < 8; i++)
        #pragma unroll
        for (int j = 0; j < 7; j++) acc[i][j] = 0ull;

    for (int stage = 0; stage < CIN/KC; stage++) {
        int ci0 = stage * KC;
        // ---- load weights: 8 ci x 9 taps x 128 co = 9216 floats, fully contiguous in g_wdyn
        {
            const float4* wsrc = (const float4*)(g_wdyn + ((size_t)b*CITAP + (size_t)ci0*TAPS) * COUT
                                                 + (size_t)ct * 0);   // co-tile handled below
            // co-tile offset: rows are 256 co wide; we need [ct*128, ct*128+128)
            const float* wrow0 = g_wdyn + ((size_t)b*CITAP + (size_t)ci0*TAPS) * COUT + ct*128;
            float4* wdst = (float4*)sW;
            (void)wsrc;
            #pragma unroll
            for (int it = 0; it < 18; it++) {
                int idx = it*128 + tid;          // 0..2303 float4 slots
                int row = idx >> 5;              // kc*9+tap (0..71)
                int c4  = idx & 31;              // float4 within 128 co
                wdst[idx] = *(const float4*)(wrow0 + (size_t)row*COUT + c4*4);
            }
        }
        // ---- load x halo tile: 8 ci x 4 rows x 58 cols (stored at [1..57], zeros at pads)
        #pragma unroll
        for (int it = 0; it < 16; it++) {
            int idx = it*128 + tid;              // 0..2047
            int kc  = idx >> 8;
            int rem = idx & 255;
            int ir  = rem >> 6;
            int jj  = rem & 63;
            int hi  = h0 - 1 + ir;
            int wc  = jj - 1;
            float v = 0.f;
            if (hi >= 0 && hi < HH && wc >= 0 && wc < WWD)
                v = x[((size_t)(b*CIN + ci0 + kc)*HH + hi)*WWD + wc];
            sX[kc][ir][jj] = v;
        }
        __syncthreads();

        // ---- compute
        for (int kc = 0; kc < KC; kc++) {
            #pragma unroll
            for (int r = 0; r < 3; r++) {
                float xv[16];
                #pragma unroll
                for (int t = 0; t < 16; t++) xv[t] = sX[kc][prow + r][col0 + t];
                #pragma unroll
                for (int s = 0; s < 3; s++) {
                    const float4* aw = (const float4*)(sW + (kc*TAPS + r*3 + s)*128 + cog*8);
                    float4 A0 = aw[0], A1 = aw[1];
                    unsigned long long ap[8];
                    ap[0] = dup2(A0.x); ap[1] = dup2(A0.y); ap[2] = dup2(A0.z); ap[3] = dup2(A0.w);
                    ap[4] = dup2(A1.x); ap[5] = dup2(A1.y); ap[6] = dup2(A1.z); ap[7] = dup2(A1.w);
                    unsigned long long bp[7];
                    #pragma unroll
                    for (int j = 0; j < 7; j++) bp[j] = pack2(xv[2*j + s], xv[2*j + s + 1]);
                    #pragma unroll
                    for (int i = 0; i < 8; i++)
                        #pragma unroll
                        for (int j = 0; j < 7; j++)
                            ffma2(acc[i][j], ap[i], bp[j]);
                }
            }
        }
        __syncthreads();
    }

    // ---- store: 8 co x 7 aligned float2 pairs
    int h = h0 + prow;
    #pragma unroll
    for (int i = 0; i < 8; i++) {
        int co = ct*128 + cog*8 + i;
        float* o = out + ((size_t)(b*COUT + co)*HH + h)*WWD + col0;
        #pragma unroll
        for (int j = 0; j < 7; j++) {
            float lo, hi2;
            unpack2(acc[i][j], lo, hi2);
            *(float2*)(o + 2*j) = make_float2(lo, hi2);
        }
    }
}

// ===================== launch =====================
extern "C" void kernel_launch(void* const* d_in, const int* in_sizes, int n_in,
                              void* d_out, int out_size) {
    const float* x    = (const float*)d_in[0];
    const float* wb   = (const float*)d_in[1];
    const float* fc1w = (const float*)d_in[2];
    const float* fc1b = (const float*)d_in[3];
    const float* fc2w = (const float*)d_in[4];
    const float* fc2b = (const float*)d_in[5];
    float* out = (float*)d_out;

    gap_kernel<<<BB*CIN, 256>>>(x);
    router_kernel<<<BB, 64>>>(fc1w, fc1b, fc2w, fc2b);
    mix_kernel<<<dim3(CIN/32, COUT/32, BB), 256>>>(wb);
    conv_kernel<<<dim3(HH/2, COUT/128, BB), 128>>>(x, out);
}

// round 3
// speedup vs baseline: 2.9082x; 2.9082x over previous
#include <cuda_runtime.h>
#include <cstdint>

#define BB   32
#define CIN  256
#define HH   56
#define WWD  56
#define COUT 256
#define NK   4
#define HID  64

#define CIC   32            // ci per stage
#define NSTG  (CIN/CIC)     // 8
#define PADW  36            // padded ci-stride (bank-conflict-free fragments)

// -------- scratch (device globals) --------
__device__ float g_v[BB*CIN];
__device__ float g_a[BB*NK];
// mixed weights (tf32 bit pattern), layout [b][tap][co][ci]
__device__ __align__(16) float g_wa[(size_t)BB*9*COUT*CIN];

// ===================== helpers =====================
__device__ __forceinline__ uint32_t smem_u32(const void* p) {
    uint32_t a;
    asm("{ .reg .u64 t; cvta.to.shared.u64 t, %1; cvt.u32.u64 %0, t; }" : "=r"(a) : "l"(p));
    return a;
}
__device__ __forceinline__ uint32_t f2tf32(float f) {
    uint32_t r;
    asm("cvt.rna.tf32.f32 %0, %1;" : "=r"(r) : "f"(f));
    return r;
}
__device__ __forceinline__ void mma_tf32(float* c, const uint32_t* a, const uint32_t* b) {
    asm volatile("mma.sync.aligned.m16n8k8.row.col.f32.tf32.tf32.f32 "
        "{%0,%1,%2,%3}, {%4,%5,%6,%7}, {%8,%9}, {%0,%1,%2,%3};"
        : "+f"(c[0]), "+f"(c[1]), "+f"(c[2]), "+f"(c[3])
        : "r"(a[0]), "r"(a[1]), "r"(a[2]), "r"(a[3]), "r"(b[0]), "r"(b[1]));
}
#define CP_ASYNC16(dst, src) \
    asm volatile("cp.async.ca.shared.global [%0], [%1], 16;" :: "r"(dst), "l"(src) : "memory")
#define CP_COMMIT() asm volatile("cp.async.commit_group;" ::: "memory")
#define CP_WAIT(n)  asm volatile("cp.async.wait_group %0;" :: "n"(n) : "memory")

// ===================== 1) global average pool =====================
__global__ void gap_kernel(const float* __restrict__ x) {
    int bc = blockIdx.x;
    const float* p = x + (size_t)bc * (HH*WWD);
    float s = 0.f;
    for (int i = threadIdx.x; i < HH*WWD; i += 256) s += p[i];
    __shared__ float red[256];
    red[threadIdx.x] = s;
    __syncthreads();
    for (int off = 128; off > 0; off >>= 1) {
        if (threadIdx.x < off) red[threadIdx.x] += red[threadIdx.x + off];
        __syncthreads();
    }
    if (threadIdx.x == 0) g_v[bc] = red[0] * (1.0f / (HH*WWD));
}

// ===================== 2) router MLP + softmax =====================
__global__ void router_kernel(const float* __restrict__ fc1w, const float* __restrict__ fc1b,
                              const float* __restrict__ fc2w, const float* __restrict__ fc2b) {
    int b = blockIdx.x;
    __shared__ float sv[CIN];
    __shared__ float sh[HID];
    __shared__ float sl[NK];
    for (int i = threadIdx.x; i < CIN; i += 64) sv[i] = g_v[b*CIN + i];
    __syncthreads();
    int j = threadIdx.x;
    float acc = fc1b[j];
    for (int c = 0; c < CIN; c++) acc += sv[c] * fc1w[j*CIN + c];
    sh[j] = acc > 0.f ? acc : 0.f;
    __syncthreads();
    if (j < NK) {
        float l = fc2b[j];
        for (int t = 0; t < HID; t++) l += sh[t] * fc2w[j*HID + t];
        sl[j] = l;
    }
    __syncthreads();
    if (j == 0) {
        float m = sl[0];
        for (int k = 1; k < NK; k++) m = fmaxf(m, sl[k]);
        float e[NK], ssum = 0.f;
        for (int k = 0; k < NK; k++) { e[k] = expf(sl[k] - m); ssum += e[k]; }
        float inv = 1.0f / ssum;
        for (int k = 0; k < NK; k++) g_a[b*NK + k] = e[k] * inv;
    }
}

// ===================== 3) mix banks -> g_wa[b][tap][co][ci] (tf32) =====================
__global__ void mix_kernel(const float* __restrict__ wb) {
    __shared__ float s[NK][CIN*9];
    int co = blockIdx.x, b = blockIdx.y;
    for (int idx = threadIdx.x; idx < NK*CIN*9; idx += 256) {
        int k = idx / (CIN*9);
        int jj = idx - k * (CIN*9);
        s[k][jj] = wb[((size_t)k*COUT + co)*(CIN*9) + jj];
    }
    float a0 = g_a[b*NK+0], a1 = g_a[b*NK+1], a2 = g_a[b*NK+2], a3 = g_a[b*NK+3];
    __syncthreads();
    for (int idx = threadIdx.x; idx < 9*CIN; idx += 256) {
        int tap = idx >> 8;
        int ci  = idx & 255;
        int src = ci*9 + tap;
        float v = a0*s[0][src] + a1*s[1][src] + a2*s[2][src] + a3*s[3][src];
        g_wa[(((size_t)b*9 + tap)*COUT + co)*CIN + ci] = __uint_as_float(f2tf32(v));
    }
}

// ===================== 4) conv: tf32 mma.sync implicit GEMM =====================
// grid (28 row-pairs, 2 co-tiles, 32 b), 256 threads (8 warps).
// Block tile: 128 co x 112 px (2 rows x 56). Warp tile: 32 co x 56 px (1 output row).
// K loop: 8 ci-stages x 9 taps x 4 k8-steps; 14 mma per warp per k8-step.

#define SX_FLOATS (4*58*PADW)              // 8352
#define SA_FLOATS (128*PADW)               // 4608 per buffer
#define SMEM_SZ   ((SX_FLOATS + 2*SA_FLOATS) * 4)   // 70272 B

__global__ void __launch_bounds__(256, 2)
conv_kernel(const float* __restrict__ x, float* __restrict__ out) {
    extern __shared__ float smem[];
    float* sx = smem;                       // [r(4)][iw(58)][ci pad 36]
    float* sA = smem + SX_FLOATS;           // [2][co(128)][ci pad 36]
    uint32_t saddrA = smem_u32(sA);

    int tid = threadIdx.x, wid = tid >> 5, lane = tid & 31;
    int lane4 = lane & 3, laneq = lane >> 2;
    int rp = blockIdx.x, ct = blockIdx.y, b = blockIdx.z;
    int h0 = rp * 2;
    int m0 = (wid & 3) * 32;                // warp co offset
    int orow = wid >> 2;                    // warp output row (0..1)

    float c[2][7][4];
    #pragma unroll
    for (int i = 0; i < 2; i++)
        #pragma unroll
        for (int j = 0; j < 7; j++)
            #pragma unroll
            for (int q = 0; q < 4; q++) c[i][j][q] = 0.f;

    for (int s = 0; s < NSTG; s++) {
        int ci0 = s * CIC;
        __syncthreads();   // everyone done with previous stage's sx/sA

        // ---- stage sx: 4 input rows x 58 cols x 32 ci, transposed + tf32-converted
        for (int u = tid; u < 4*32*14; u += 256) {
            int r  = u / (32*14);
            int rm = u - r * (32*14);
            int ci = rm / 14;
            int q  = rm - ci * 14;
            int h  = h0 - 1 + r;
            float4 v = make_float4(0.f, 0.f, 0.f, 0.f);
            if (h >= 0 && h < HH)
                v = *(const float4*)(x + ((size_t)(b*CIN + ci0 + ci)*HH + h)*WWD + q*4);
            float* d = sx + (r*58 + 1 + q*4)*PADW + ci;
            d[0*PADW] = __uint_as_float(f2tf32(v.x));
            d[1*PADW] = __uint_as_float(f2tf32(v.y));
            d[2*PADW] = __uint_as_float(f2tf32(v.z));
            d[3*PADW] = __uint_as_float(f2tf32(v.w));
        }
        for (int u = tid; u < 4*2*32; u += 256) {
            int r  = u >> 6;
            int rm = u & 63;
            int e  = rm >> 5;
            int ci = rm & 31;
            sx[(r*58 + e*57)*PADW + ci] = 0.f;
        }

        // ---- prefetch A for tap 0 into buf 0
        {
            const float* abase = g_wa + (((size_t)b*9 + 0)*COUT + ct*128)*CIN + ci0;
            #pragma unroll
            for (int it = 0; it < 4; it++) {
                int u = it*256 + tid;        // 0..1023
                int row = u >> 3, q = u & 7;
                CP_ASYNC16(saddrA + (uint32_t)((row*PADW + q*4) * 4),
                           abase + (size_t)row*CIN + q*4);
            }
            CP_COMMIT();
        }

        for (int t = 0; t < 9; t++) {
            int buf = t & 1;
            if (t < 8) {   // prefetch next tap into other buffer
                const float* abase = g_wa + (((size_t)b*9 + (t+1))*COUT + ct*128)*CIN + ci0;
                uint32_t dstb = saddrA + (uint32_t)(((t+1) & 1) * SA_FLOATS * 4);
                #pragma unroll
                for (int it = 0; it < 4; it++) {
                    int u = it*256 + tid;
                    int row = u >> 3, q = u & 7;
                    CP_ASYNC16(dstb + (uint32_t)((row*PADW + q*4) * 4),
                               abase + (size_t)row*CIN + q*4);
                }
                CP_COMMIT();
                CP_WAIT(1);
            } else {
                CP_WAIT(0);
            }
            __syncthreads();   // sx (t==0) + sA[buf] visible to all

            int dy = t / 3, dx = t - dy * 3;
            const float* sxw = sx + ((orow + dy)*58 + dx) * PADW;
            const float* sAb = sA + buf * SA_FLOATS;

            #pragma unroll
            for (int kk = 0; kk < 4; kk++) {
                int k0 = kk * 8;
                uint32_t a[2][4];
                #pragma unroll
                for (int mt = 0; mt < 2; mt++) {
                    int r0 = m0 + mt*16 + laneq;
                    a[mt][0] = __float_as_uint(sAb[(r0    )*PADW + k0     + lane4]);
                    a[mt][1] = __float_as_uint(sAb[(r0 + 8)*PADW + k0     + lane4]);
                    a[mt][2] = __float_as_uint(sAb[(r0    )*PADW + k0 + 4 + lane4]);
                    a[mt][3] = __float_as_uint(sAb[(r0 + 8)*PADW + k0 + 4 + lane4]);
                }
                #pragma unroll
                for (int nt = 0; nt < 7; nt++) {
                    uint32_t bf[2];
                    int col = nt*8 + laneq;
                    bf[0] = __float_as_uint(sxw[col*PADW + k0     + lane4]);
                    bf[1] = __float_as_uint(sxw[col*PADW + k0 + 4 + lane4]);
                    mma_tf32(c[0][nt], a[0], bf);
                    mma_tf32(c[1][nt], a[1], bf);
                }
            }
            __syncthreads();   // compute done before buf is overwritten / sx restaged
        }
    }

    // ---- epilogue: float2 stores (cols (lane%4)*2, +1)
    int h = h0 + orow;
    #pragma unroll
    for (int mt = 0; mt < 2; mt++) {
        int co_base = ct*128 + m0 + mt*16 + laneq;
        #pragma unroll
        for (int half = 0; half < 2; half++) {
            int co = co_base + half*8;
            float* plane = out + ((size_t)(b*COUT + co)*HH + h)*WWD;
            #pragma unroll
            for (int nt = 0; nt < 7; nt++) {
                int wcol = nt*8 + lane4*2;
                *(float2*)(plane + wcol) = make_float2(c[mt][nt][half*2], c[mt][nt][half*2 + 1]);
            }
        }
    }
}

// ===================== launch =====================
extern "C" void kernel_launch(void* const* d_in, const int* in_sizes, int n_in,
                              void* d_out, int out_size) {
    const float* x    = (const float*)d_in[0];
    const float* wb   = (const float*)d_in[1];
    const float* fc1w = (const float*)d_in[2];
    const float* fc1b = (const float*)d_in[3];
    const float* fc2w = (const float*)d_in[4];
    const float* fc2b = (const float*)d_in[5];
    float* out = (float*)d_out;

    cudaFuncSetAttribute(conv_kernel, cudaFuncAttributeMaxDynamicSharedMemorySize, SMEM_SZ);

    gap_kernel<<<BB*CIN, 256>>>(x);
    router_kernel<<<BB, 64>>>(fc1w, fc1b, fc2w, fc2b);
    mix_kernel<<<dim3(COUT, BB), 256>>>(wb);
    conv_kernel<<<dim3(28, 2, BB), 256, SMEM_SZ>>>(x, out);
}

// round 4
// speedup vs baseline: 3.0766x; 1.0579x over previous
#include <cuda_runtime.h>
#include <cstdint>

#define BB   32
#define CIN  256
#define HH   56
#define WWD  56
#define COUT 256
#define NK   4
#define HID  64

#define CIC   32            // ci per stage
#define NSTG  (CIN/CIC)     // 8
#define PADW  40            // padded ci-stride in sx (conflict-free v2 fragments)
#define NROWS 4             // output rows per CTA
#define NTAP  72            // NSTG*9 global tap steps

// -------- scratch (device globals) --------
__device__ float g_v[BB*CIN];
__device__ float g_a[BB*NK];
// mixed weights (tf32), fragment-permuted:
// [b][tap][half(2)][stage(8)][co_t(8)][k_t(4)][lane(32)][v(4)]
__device__ __align__(16) float g_wa[(size_t)BB*9*COUT*CIN];

// ===================== helpers =====================
__device__ __forceinline__ uint32_t smem_u32(const void* p) {
    uint32_t a;
    asm("{ .reg .u64 t; cvta.to.shared.u64 t, %1; cvt.u32.u64 %0, t; }" : "=r"(a) : "l"(p));
    return a;
}
__device__ __forceinline__ uint32_t f2tf32(float f) {
    uint32_t r;
    asm("cvt.rna.tf32.f32 %0, %1;" : "=r"(r) : "f"(f));
    return r;
}
__device__ __forceinline__ void mma_tf32(float* c, const uint32_t* a, const uint32_t* b) {
    asm volatile("mma.sync.aligned.m16n8k8.row.col.f32.tf32.tf32.f32 "
        "{%0,%1,%2,%3}, {%4,%5,%6,%7}, {%8,%9}, {%0,%1,%2,%3};"
        : "+f"(c[0]), "+f"(c[1]), "+f"(c[2]), "+f"(c[3])
        : "r"(a[0]), "r"(a[1]), "r"(a[2]), "r"(a[3]), "r"(b[0]), "r"(b[1]));
}
#define CP_ASYNC16(dst, src) \
    asm volatile("cp.async.ca.shared.global [%0], [%1], 16;" :: "r"(dst), "l"(src) : "memory")
#define CP_COMMIT() asm volatile("cp.async.commit_group;" ::: "memory")
#define CP_WAIT(n)  asm volatile("cp.async.wait_group %0;" :: "n"(n) : "memory")

#define LDSV4(r0,r1,r2,r3,a) \
    asm volatile("ld.shared.v4.u32 {%0,%1,%2,%3}, [%4];" : "=r"(r0),"=r"(r1),"=r"(r2),"=r"(r3) : "r"(a))
#define LDSV2(r0,r1,a) \
    asm volatile("ld.shared.v2.u32 {%0,%1}, [%2];" : "=r"(r0),"=r"(r1) : "r"(a))

// ===================== 1) global average pool =====================
__global__ void gap_kernel(const float* __restrict__ x) {
    int bc = blockIdx.x;
    const float* p = x + (size_t)bc * (HH*WWD);
    float s = 0.f;
    for (int i = threadIdx.x; i < HH*WWD; i += 256) s += p[i];
    __shared__ float red[256];
    red[threadIdx.x] = s;
    __syncthreads();
    for (int off = 128; off > 0; off >>= 1) {
        if (threadIdx.x < off) red[threadIdx.x] += red[threadIdx.x + off];
        __syncthreads();
    }
    if (threadIdx.x == 0) g_v[bc] = red[0] * (1.0f / (HH*WWD));
}

// ===================== 2) router MLP + softmax =====================
__global__ void router_kernel(const float* __restrict__ fc1w, const float* __restrict__ fc1b,
                              const float* __restrict__ fc2w, const float* __restrict__ fc2b) {
    int b = blockIdx.x;
    __shared__ float sv[CIN];
    __shared__ float sh[HID];
    __shared__ float sl[NK];
    for (int i = threadIdx.x; i < CIN; i += 64) sv[i] = g_v[b*CIN + i];
    __syncthreads();
    int j = threadIdx.x;
    float acc = fc1b[j];
    for (int c = 0; c < CIN; c++) acc += sv[c] * fc1w[j*CIN + c];
    sh[j] = acc > 0.f ? acc : 0.f;
    __syncthreads();
    if (j < NK) {
        float l = fc2b[j];
        for (int t = 0; t < HID; t++) l += sh[t] * fc2w[j*HID + t];
        sl[j] = l;
    }
    __syncthreads();
    if (j == 0) {
        float m = sl[0];
        for (int k = 1; k < NK; k++) m = fmaxf(m, sl[k]);
        float e[NK], ssum = 0.f;
        for (int k = 0; k < NK; k++) { e[k] = expf(sl[k] - m); ssum += e[k]; }
        float inv = 1.0f / ssum;
        for (int k = 0; k < NK; k++) g_a[b*NK + k] = e[k] * inv;
    }
}

// ===================== 3) mix banks -> fragment-permuted g_wa (tf32) =====================
__global__ void mix_kernel(const float* __restrict__ wb) {
    __shared__ float s[NK][CIN*9];
    int co = blockIdx.x, b = blockIdx.y;
    for (int idx = threadIdx.x; idx < NK*CIN*9; idx += 256) {
        int k = idx / (CIN*9);
        int jj = idx - k * (CIN*9);
        s[k][jj] = wb[((size_t)k*COUT + co)*(CIN*9) + jj];
    }
    float a0 = g_a[b*NK+0], a1 = g_a[b*NK+1], a2 = g_a[b*NK+2], a3 = g_a[b*NK+3];
    int half = co >> 7, co_t = (co >> 4) & 7, r = co & 15;
    __syncthreads();
    for (int idx = threadIdx.x; idx < 9*CIN; idx += 256) {
        int tap = idx >> 8;
        int ci  = idx & 255;
        int src = ci*9 + tap;
        float v = a0*s[0][src] + a1*s[1][src] + a2*s[2][src] + a3*s[3][src];
        int stage = ci >> 5, k_t = (ci >> 3) & 3, cc = ci & 7;
        int lane = (r & 7)*4 + (cc & 3);
        int vv   = ((r >> 3) & 1) + 2*((cc >> 2) & 1);
        size_t dst = ((((((((size_t)b*9 + tap)*2 + half)*8 + stage)*8 + co_t)*4 + k_t)*32 + lane)*4) + vv;
        g_wa[dst] = __uint_as_float(f2tf32(v));
    }
}

// ===================== 4) conv: tf32 mma.sync implicit GEMM =====================
// grid (14 row-quads, 2 co-halves, 32 b), 256 threads (8 warps).
// Block tile: 128 co x (4 rows x 56). Warp tile: 64 co x 56 px (4 m16 x 7 n8 tiles).

#define SX_FLOATS (6*58*PADW)               // 13920
#define SA_FLOATS (128*32)                  // 4096 per buffer (tiled layout)
#define SMEM_SZ   ((SX_FLOATS + 2*SA_FLOATS) * 4)   // 88448 B

__global__ void __launch_bounds__(256, 1)
conv_kernel(const float* __restrict__ x, float* __restrict__ out) {
    extern __shared__ float smem[];
    float* sx = smem;                        // [r(6)][iw(58)][ci_perm pad 40]
    float* sA = smem + SX_FLOATS;            // [2][co_t(8)][k_t(4)][lane(32)][4]
    uint32_t sxaddr = smem_u32(sx);
    uint32_t saddrA = smem_u32(sA);

    int tid = threadIdx.x, wid = tid >> 5, lane = tid & 31;
    int lane4 = lane & 3, laneq = lane >> 2;
    int nt4 = blockIdx.x, ct = blockIdx.y, b = blockIdx.z;
    int h0 = nt4 * NROWS;
    int mhalf = wid & 1;                     // co 64-half within the 128 tile
    int orow  = wid >> 1;                    // output row 0..3

    float c[4][7][4];
    #pragma unroll
    for (int i = 0; i < 4; i++)
        #pragma unroll
        for (int j = 0; j < 7; j++)
            #pragma unroll
            for (int q = 0; q < 4; q++) c[i][j][q] = 0.f;

    // initial A prefetch (g=0) into buf 0
    {
        const float* src = g_wa + ((((size_t)b*9 + 0)*2 + ct)*8 + 0) * (size_t)SA_FLOATS;
        #pragma unroll
        for (int it = 0; it < 4; it++) {
            int u = it*256 + tid;
            CP_ASYNC16(saddrA + (uint32_t)(u*16), src + u*4);
        }
        CP_COMMIT();
    }

    for (int s = 0; s < NSTG; s++) {
        int ci0 = s * CIC;
        // ---- stage sx: 6 rows x 58 cols x 32 ci (k-interleaved), tf32-converted
        // u -> (r, q, ci) with ci fastest: conflict-free STS
        for (int u = tid; u < 6*14*32; u += 256) {
            int r  = u / (14*32);
            int rm = u - r * (14*32);
            int q  = rm >> 5;
            int ci = rm & 31;
            int h  = h0 - 1 + r;
            float4 v = make_float4(0.f, 0.f, 0.f, 0.f);
            if (h >= 0 && h < HH)
                v = *(const float4*)(x + ((size_t)(b*CIN + ci0 + ci)*HH + h)*WWD + q*4);
            int p = (ci & 24) + (ci & 3)*2 + ((ci >> 2) & 1);
            float* d = sx + (r*58 + 1 + q*4)*PADW + p;
            d[0*PADW] = __uint_as_float(f2tf32(v.x));
            d[1*PADW] = __uint_as_float(f2tf32(v.y));
            d[2*PADW] = __uint_as_float(f2tf32(v.z));
            d[3*PADW] = __uint_as_float(f2tf32(v.w));
        }
        for (int u = tid; u < 6*2*32; u += 256) {
            int r  = u >> 6;
            int rm = u & 63;
            int e  = rm >> 5;
            int ci = rm & 31;
            sx[(r*58 + e*57)*PADW + ci] = 0.f;
        }

        for (int t = 0; t < 9; t++) {
            int g = s*9 + t;
            int buf = g & 1;
            // prefetch next tap (possibly next stage's tap 0) into other buffer
            if (g + 1 < NTAP) {
                int gn = g + 1;
                int sn = gn / 9, tn = gn - sn*9;
                const float* src = g_wa + ((((size_t)b*9 + tn)*2 + ct)*8 + sn) * (size_t)SA_FLOATS;
                uint32_t dstb = saddrA + (uint32_t)(((gn & 1) * SA_FLOATS) * 4);
                #pragma unroll
                for (int it = 0; it < 4; it++) {
                    int u = it*256 + tid;
                    CP_ASYNC16(dstb + (uint32_t)(u*16), src + u*4);
                }
                CP_COMMIT();
                CP_WAIT(1);
            } else {
                CP_WAIT(0);
            }
            __syncthreads();   // sA[buf] + (t==0: sx) visible

            int dy = t / 3, dx = t - dy * 3;
            uint32_t sxw = sxaddr + (uint32_t)((((orow + dy)*58 + dx) * PADW) * 4);
            uint32_t sAb = saddrA + (uint32_t)((buf * SA_FLOATS) * 4);

            #pragma unroll
            for (int kk = 0; kk < 4; kk++) {
                uint32_t a[4][4];
                #pragma unroll
                for (int mt = 0; mt < 2; mt++) {  // declare pairs to help scheduling
                    int ct0 = mhalf*4 + mt*2;
                    LDSV4(a[mt*2][0], a[mt*2][1], a[mt*2][2], a[mt*2][3],
                          sAb + (uint32_t)((((ct0    )*4 + kk)*32 + lane)*16));
                    LDSV4(a[mt*2+1][0], a[mt*2+1][1], a[mt*2+1][2], a[mt*2+1][3],
                          sAb + (uint32_t)((((ct0 + 1)*4 + kk)*32 + lane)*16));
                }
                #pragma unroll
                for (int nt = 0; nt < 7; nt++) {
                    uint32_t bf[2];
                    int col = nt*8 + laneq;
                    LDSV2(bf[0], bf[1], sxw + (uint32_t)((col*PADW + kk*8 + lane4*2) * 4));
                    mma_tf32(c[0][nt], a[0], bf);
                    mma_tf32(c[1][nt], a[1], bf);
                    mma_tf32(c[2][nt], a[2], bf);
                    mma_tf32(c[3][nt], a[3], bf);
                }
            }
            __syncthreads();   // release sA[buf] / sx before overwrite
        }
    }

    // ---- epilogue: float2 stores
    int h = h0 + orow;
    #pragma unroll
    for (int mt = 0; mt < 4; mt++) {
        int co_base = ct*128 + mhalf*64 + mt*16 + laneq;
        #pragma unroll
        for (int half = 0; half < 2; half++) {
            int co = co_base + half*8;
            float* plane = out + ((size_t)(b*COUT + co)*HH + h)*WWD;
            #pragma unroll
            for (int nt = 0; nt < 7; nt++) {
                int wcol = nt*8 + lane4*2;
                *(float2*)(plane + wcol) = make_float2(c[mt][nt][half*2], c[mt][nt][half*2 + 1]);
            }
        }
    }
}

// ===================== launch =====================
extern "C" void kernel_launch(void* const* d_in, const int* in_sizes, int n_in,
                              void* d_out, int out_size) {
    const float* x    = (const float*)d_in[0];
    const float* wb   = (const float*)d_in[1];
    const float* fc1w = (const float*)d_in[2];
    const float* fc1b = (const float*)d_in[3];
    const float* fc2w = (const float*)d_in[4];
    const float* fc2b = (const float*)d_in[5];
    float* out = (float*)d_out;

    cudaFuncSetAttribute(conv_kernel, cudaFuncAttributeMaxDynamicSharedMemorySize, SMEM_SZ);

    gap_kernel<<<BB*CIN, 256>>>(x);
    router_kernel<<<BB, 64>>>(fc1w, fc1b, fc2w, fc2b);
    mix_kernel<<<dim3(COUT, BB), 256>>>(wb);
    conv_kernel<<<dim3(HH/NROWS, 2, BB), 256, SMEM_SZ>>>(x, out);
}

// round 5
// speedup vs baseline: 3.0932x; 1.0054x over previous
#include <cuda_runtime.h>
#include <cstdint>

#define BB   32
#define CIN  256
#define HH   56
#define WWD  56
#define COUT 256
#define NK   4
#define HID  64

#define CIC   32            // ci per stage
#define NSTG  (CIN/CIC)     // 8
#define PADW  40            // padded ci-stride in sx (conflict-free v2 fragments)
#define NROWS 4             // output rows per CTA
#define NTAP  72            // NSTG*9 global tap steps

// -------- scratch (device globals) --------
__device__ float g_v[BB*CIN];
__device__ float g_a[BB*NK];
// mixed weights (tf32), fragment-permuted:
// [b][tap][half(2)][stage(8)][co_t(8)][k_t(4)][lane(32)][v(4)]
__device__ __align__(16) float g_wa[(size_t)BB*9*COUT*CIN];

// ===================== helpers =====================
__device__ __forceinline__ uint32_t smem_u32(const void* p) {
    uint32_t a;
    asm("{ .reg .u64 t; cvta.to.shared.u64 t, %1; cvt.u32.u64 %0, t; }" : "=r"(a) : "l"(p));
    return a;
}
__device__ __forceinline__ uint32_t f2tf32(float f) {
    uint32_t r;
    asm("cvt.rna.tf32.f32 %0, %1;" : "=r"(r) : "f"(f));
    return r;
}
__device__ __forceinline__ void mma_tf32(float* c, const uint32_t* a, const uint32_t* b) {
    asm volatile("mma.sync.aligned.m16n8k8.row.col.f32.tf32.tf32.f32 "
        "{%0,%1,%2,%3}, {%4,%5,%6,%7}, {%8,%9}, {%0,%1,%2,%3};"
        : "+f"(c[0]), "+f"(c[1]), "+f"(c[2]), "+f"(c[3])
        : "r"(a[0]), "r"(a[1]), "r"(a[2]), "r"(a[3]), "r"(b[0]), "r"(b[1]));
}
#define CP_ASYNC16(dst, src) \
    asm volatile("cp.async.ca.shared.global [%0], [%1], 16;" :: "r"(dst), "l"(src) : "memory")
#define CP_COMMIT() asm volatile("cp.async.commit_group;" ::: "memory")
#define CP_WAIT(n)  asm volatile("cp.async.wait_group %0;" :: "n"(n) : "memory")

#define LDSV4(r0,r1,r2,r3,a) \
    asm volatile("ld.shared.v4.u32 {%0,%1,%2,%3}, [%4];" : "=r"(r0),"=r"(r1),"=r"(r2),"=r"(r3) : "r"(a))
#define LDSV2(r0,r1,a) \
    asm volatile("ld.shared.v2.u32 {%0,%1}, [%2];" : "=r"(r0),"=r"(r1) : "r"(a))

// ===================== 1) global average pool =====================
__global__ void gap_kernel(const float* __restrict__ x) {
    int bc = blockIdx.x;
    const float* p = x + (size_t)bc * (HH*WWD);
    float s = 0.f;
    for (int i = threadIdx.x; i < HH*WWD; i += 256) s += p[i];
    __shared__ float red[256];
    red[threadIdx.x] = s;
    __syncthreads();
    for (int off = 128; off > 0; off >>= 1) {
        if (threadIdx.x < off) red[threadIdx.x] += red[threadIdx.x + off];
        __syncthreads();
    }
    if (threadIdx.x == 0) g_v[bc] = red[0] * (1.0f / (HH*WWD));
}

// ===================== 2) router MLP + softmax =====================
__global__ void router_kernel(const float* __restrict__ fc1w, const float* __restrict__ fc1b,
                              const float* __restrict__ fc2w, const float* __restrict__ fc2b) {
    int b = blockIdx.x;
    __shared__ float sv[CIN];
    __shared__ float sh[HID];
    __shared__ float sl[NK];
    for (int i = threadIdx.x; i < CIN; i += 64) sv[i] = g_v[b*CIN + i];
    __syncthreads();
    int j = threadIdx.x;
    float acc = fc1b[j];
    for (int c = 0; c < CIN; c++) acc += sv[c] * fc1w[j*CIN + c];
    sh[j] = acc > 0.f ? acc : 0.f;
    __syncthreads();
    if (j < NK) {
        float l = fc2b[j];
        for (int t = 0; t < HID; t++) l += sh[t] * fc2w[j*HID + t];
        sl[j] = l;
    }
    __syncthreads();
    if (j == 0) {
        float m = sl[0];
        for (int k = 1; k < NK; k++) m = fmaxf(m, sl[k]);
        float e[NK], ssum = 0.f;
        for (int k = 0; k < NK; k++) { e[k] = expf(sl[k] - m); ssum += e[k]; }
        float inv = 1.0f / ssum;
        for (int k = 0; k < NK; k++) g_a[b*NK + k] = e[k] * inv;
    }
}

// ===================== 3) mix banks -> fragment-permuted g_wa (tf32) =====================
__global__ void mix_kernel(const float* __restrict__ wb) {
    __shared__ float s[NK][CIN*9];
    int co = blockIdx.x, b = blockIdx.y;
    for (int idx = threadIdx.x; idx < NK*CIN*9; idx += 256) {
        int k = idx / (CIN*9);
        int jj = idx - k * (CIN*9);
        s[k][jj] = wb[((size_t)k*COUT + co)*(CIN*9) + jj];
    }
    float a0 = g_a[b*NK+0], a1 = g_a[b*NK+1], a2 = g_a[b*NK+2], a3 = g_a[b*NK+3];
    int half = co >> 7, co_t = (co >> 4) & 7, r = co & 15;
    __syncthreads();
    for (int idx = threadIdx.x; idx < 9*CIN; idx += 256) {
        int tap = idx >> 8;
        int ci  = idx & 255;
        int src = ci*9 + tap;
        float v = a0*s[0][src] + a1*s[1][src] + a2*s[2][src] + a3*s[3][src];
        int stage = ci >> 5, k_t = (ci >> 3) & 3, cc = ci & 7;
        int lane = (r & 7)*4 + (cc & 3);
        int vv   = ((r >> 3) & 1) + 2*((cc >> 2) & 1);
        size_t dst = ((((((((size_t)b*9 + tap)*2 + half)*8 + stage)*8 + co_t)*4 + k_t)*32 + lane)*4) + vv;
        g_wa[dst] = __uint_as_float(f2tf32(v));
    }
}

// ===================== 4) conv: tf32 mma.sync implicit GEMM =====================
// grid (14 row-quads, 2 co-halves, 32 b), 256 threads (8 warps).
// Block tile: 128 co x (4 rows x 56). Warp tile: 64 co x 56 px (4 m16 x 7 n8 tiles).

#define SX_FLOATS (6*58*PADW)               // 13920
#define SA_FLOATS (128*32)                  // 4096 per buffer (tiled layout)
#define SMEM_SZ   ((SX_FLOATS + 2*SA_FLOATS) * 4)   // 88448 B

__global__ void __launch_bounds__(256, 1)
conv_kernel(const float* __restrict__ x, float* __restrict__ out) {
    extern __shared__ float smem[];
    float* sx = smem;                        // [r(6)][iw(58)][ci_perm pad 40]
    float* sA = smem + SX_FLOATS;            // [2][co_t(8)][k_t(4)][lane(32)][4]
    uint32_t sxaddr = smem_u32(sx);
    uint32_t saddrA = smem_u32(sA);

    int tid = threadIdx.x, wid = tid >> 5, lane = tid & 31;
    int lane4 = lane & 3, laneq = lane >> 2;
    int nt4 = blockIdx.x, ct = blockIdx.y, b = blockIdx.z;
    int h0 = nt4 * NROWS;
    int mhalf = wid & 1;                     // co 64-half within the 128 tile
    int orow  = wid >> 1;                    // output row 0..3

    float c[4][7][4];
    #pragma unroll
    for (int i = 0; i < 4; i++)
        #pragma unroll
        for (int j = 0; j < 7; j++)
            #pragma unroll
            for (int q = 0; q < 4; q++) c[i][j][q] = 0.f;

    // initial A prefetch (g=0) into buf 0
    {
        const float* src = g_wa + ((((size_t)b*9 + 0)*2 + ct)*8 + 0) * (size_t)SA_FLOATS;
        #pragma unroll
        for (int it = 0; it < 4; it++) {
            int u = it*256 + tid;
            CP_ASYNC16(saddrA + (uint32_t)(u*16), src + u*4);
        }
        CP_COMMIT();
    }

    for (int s = 0; s < NSTG; s++) {
        int ci0 = s * CIC;
        // ---- stage sx: 6 rows x 58 cols x 32 ci (k-interleaved), tf32-converted
        // u -> (r, q, ci) with ci fastest: conflict-free STS
        for (int u = tid; u < 6*14*32; u += 256) {
            int r  = u / (14*32);
            int rm = u - r * (14*32);
            int q  = rm >> 5;
            int ci = rm & 31;
            int h  = h0 - 1 + r;
            float4 v = make_float4(0.f, 0.f, 0.f, 0.f);
            if (h >= 0 && h < HH)
                v = *(const float4*)(x + ((size_t)(b*CIN + ci0 + ci)*HH + h)*WWD + q*4);
            int p = (ci & 24) + (ci & 3)*2 + ((ci >> 2) & 1);
            float* d = sx + (r*58 + 1 + q*4)*PADW + p;
            d[0*PADW] = __uint_as_float(f2tf32(v.x));
            d[1*PADW] = __uint_as_float(f2tf32(v.y));
            d[2*PADW] = __uint_as_float(f2tf32(v.z));
            d[3*PADW] = __uint_as_float(f2tf32(v.w));
        }
        for (int u = tid; u < 6*2*32; u += 256) {
            int r  = u >> 6;
            int rm = u & 63;
            int e  = rm >> 5;
            int ci = rm & 31;
            sx[(r*58 + e*57)*PADW + ci] = 0.f;
        }

        for (int t = 0; t < 9; t++) {
            int g = s*9 + t;
            int buf = g & 1;
            // prefetch next tap (possibly next stage's tap 0) into other buffer
            if (g + 1 < NTAP) {
                int gn = g + 1;
                int sn = gn / 9, tn = gn - sn*9;
                const float* src = g_wa + ((((size_t)b*9 + tn)*2 + ct)*8 + sn) * (size_t)SA_FLOATS;
                uint32_t dstb = saddrA + (uint32_t)(((gn & 1) * SA_FLOATS) * 4);
                #pragma unroll
                for (int it = 0; it < 4; it++) {
                    int u = it*256 + tid;
                    CP_ASYNC16(dstb + (uint32_t)(u*16), src + u*4);
                }
                CP_COMMIT();
                CP_WAIT(1);
            } else {
                CP_WAIT(0);
            }
            __syncthreads();   // sA[buf] + (t==0: sx) visible

            int dy = t / 3, dx = t - dy * 3;
            uint32_t sxw = sxaddr + (uint32_t)((((orow + dy)*58 + dx) * PADW) * 4);
            uint32_t sAb = saddrA + (uint32_t)((buf * SA_FLOATS) * 4);

            #pragma unroll
            for (int kk = 0; kk < 4; kk++) {
                uint32_t a[4][4];
                #pragma unroll
                for (int mt = 0; mt < 2; mt++) {  // declare pairs to help scheduling
                    int ct0 = mhalf*4 + mt*2;
                    LDSV4(a[mt*2][0], a[mt*2][1], a[mt*2][2], a[mt*2][3],
                          sAb + (uint32_t)((((ct0    )*4 + kk)*32 + lane)*16));
                    LDSV4(a[mt*2+1][0], a[mt*2+1][1], a[mt*2+1][2], a[mt*2+1][3],
                          sAb + (uint32_t)((((ct0 + 1)*4 + kk)*32 + lane)*16));
                }
                #pragma unroll
                for (int nt = 0; nt < 7; nt++) {
                    uint32_t bf[2];
                    int col = nt*8 + laneq;
                    LDSV2(bf[0], bf[1], sxw + (uint32_t)((col*PADW + kk*8 + lane4*2) * 4));
                    mma_tf32(c[0][nt], a[0], bf);
                    mma_tf32(c[1][nt], a[1], bf);
                    mma_tf32(c[2][nt], a[2], bf);
                    mma_tf32(c[3][nt], a[3], bf);
                }
            }
            __syncthreads();   // release sA[buf] / sx before overwrite
        }
    }

    // ---- epilogue: float2 stores
    int h = h0 + orow;
    #pragma unroll
    for (int mt = 0; mt < 4; mt++) {
        int co_base = ct*128 + mhalf*64 + mt*16 + laneq;
        #pragma unroll
        for (int half = 0; half < 2; half++) {
            int co = co_base + half*8;
            float* plane = out + ((size_t)(b*COUT + co)*HH + h)*WWD;
            #pragma unroll
            for (int nt = 0; nt < 7; nt++) {
                int wcol = nt*8 + lane4*2;
                *(float2*)(plane + wcol) = make_float2(c[mt][nt][half*2], c[mt][nt][half*2 + 1]);
            }
        }
    }
}

// ===================== launch =====================
extern "C" void kernel_launch(void* const* d_in, const int* in_sizes, int n_in,
                              void* d_out, int out_size) {
    const float* x    = (const float*)d_in[0];
    const float* wb   = (const float*)d_in[1];
    const float* fc1w = (const float*)d_in[2];
    const float* fc1b = (const float*)d_in[3];
    const float* fc2w = (const float*)d_in[4];
    const float* fc2b = (const float*)d_in[5];
    float* out = (float*)d_out;

    cudaFuncSetAttribute(conv_kernel, cudaFuncAttributeMaxDynamicSharedMemorySize, SMEM_SZ);

    gap_kernel<<<BB*CIN, 256>>>(x);
    router_kernel<<<BB, 64>>>(fc1w, fc1b, fc2w, fc2b);
    mix_kernel<<<dim3(COUT, BB), 256>>>(wb);
    conv_kernel<<<dim3(HH/NROWS, 2, BB), 256, SMEM_SZ>>>(x, out);
}

// round 6
// speedup vs baseline: 3.2651x; 1.0556x over previous
#include <cuda_runtime.h>
#include <cstdint>

#define BB   32
#define CIN  256
#define HH   56
#define WWD  56
#define COUT 256
#define NK   4
#define HID  64

#define CIC   32            // ci per stage
#define NSTG  (CIN/CIC)     // 8
#define PADW  40            // padded ci-stride in sx
#define NROWS 4             // output rows per CTA
#define NTAP  72            // NSTG*9 global tap steps

// -------- scratch (device globals) --------
__device__ float g_v[BB*CIN];
__device__ float g_a[BB*NK];
// mixed weights (tf32), fragment-permuted:
// [b][tap][ct(4)][stage(8)][co_t(4)][k_t(4)][lane(32)][v(4)]
__device__ __align__(16) float g_wa[(size_t)BB*9*COUT*CIN];

// ===================== helpers =====================
__device__ __forceinline__ uint32_t smem_u32(const void* p) {
    uint32_t a;
    asm("{ .reg .u64 t; cvta.to.shared.u64 t, %1; cvt.u32.u64 %0, t; }" : "=r"(a) : "l"(p));
    return a;
}
__device__ __forceinline__ uint32_t f2tf32(float f) {
    uint32_t r;
    asm("cvt.rna.tf32.f32 %0, %1;" : "=r"(r) : "f"(f));
    return r;
}
__device__ __forceinline__ void mma_tf32(float* c, const uint32_t* a, const uint32_t* b) {
    asm volatile("mma.sync.aligned.m16n8k8.row.col.f32.tf32.tf32.f32 "
        "{%0,%1,%2,%3}, {%4,%5,%6,%7}, {%8,%9}, {%0,%1,%2,%3};"
        : "+f"(c[0]), "+f"(c[1]), "+f"(c[2]), "+f"(c[3])
        : "r"(a[0]), "r"(a[1]), "r"(a[2]), "r"(a[3]), "r"(b[0]), "r"(b[1]));
}
#define CP_ASYNC16(dst, src) \
    asm volatile("cp.async.ca.shared.global [%0], [%1], 16;" :: "r"(dst), "l"(src) : "memory")
#define CP_COMMIT() asm volatile("cp.async.commit_group;" ::: "memory")
#define CP_WAIT0()  asm volatile("cp.async.wait_group 0;" ::: "memory")

#define LDSV4(r0,r1,r2,r3,a) \
    asm volatile("ld.shared.v4.u32 {%0,%1,%2,%3}, [%4];" : "=r"(r0),"=r"(r1),"=r"(r2),"=r"(r3) : "r"(a))
#define LDSV2(r0,r1,a) \
    asm volatile("ld.shared.v2.u32 {%0,%1}, [%2];" : "=r"(r0),"=r"(r1) : "r"(a))

// ===================== 1) global average pool =====================
__global__ void gap_kernel(const float* __restrict__ x) {
    int bc = blockIdx.x;
    const float* p = x + (size_t)bc * (HH*WWD);
    float s = 0.f;
    for (int i = threadIdx.x; i < HH*WWD; i += 256) s += p[i];
    __shared__ float red[256];
    red[threadIdx.x] = s;
    __syncthreads();
    for (int off = 128; off > 0; off >>= 1) {
        if (threadIdx.x < off) red[threadIdx.x] += red[threadIdx.x + off];
        __syncthreads();
    }
    if (threadIdx.x == 0) g_v[bc] = red[0] * (1.0f / (HH*WWD));
}

// ===================== 2) router MLP + softmax =====================
__global__ void router_kernel(const float* __restrict__ fc1w, const float* __restrict__ fc1b,
                              const float* __restrict__ fc2w, const float* __restrict__ fc2b) {
    int b = blockIdx.x;
    __shared__ float sv[CIN];
    __shared__ float sh[HID];
    __shared__ float sl[NK];
    for (int i = threadIdx.x; i < CIN; i += 64) sv[i] = g_v[b*CIN + i];
    __syncthreads();
    int j = threadIdx.x;
    float acc = fc1b[j];
    for (int c = 0; c < CIN; c++) acc += sv[c] * fc1w[j*CIN + c];
    sh[j] = acc > 0.f ? acc : 0.f;
    __syncthreads();
    if (j < NK) {
        float l = fc2b[j];
        for (int t = 0; t < HID; t++) l += sh[t] * fc2w[j*HID + t];
        sl[j] = l;
    }
    __syncthreads();
    if (j == 0) {
        float m = sl[0];
        for (int k = 1; k < NK; k++) m = fmaxf(m, sl[k]);
        float e[NK], ssum = 0.f;
        for (int k = 0; k < NK; k++) { e[k] = expf(sl[k] - m); ssum += e[k]; }
        float inv = 1.0f / ssum;
        for (int k = 0; k < NK; k++) g_a[b*NK + k] = e[k] * inv;
    }
}

// ===================== 3) mix banks -> fragment-permuted g_wa (tf32) =====================
__global__ void mix_kernel(const float* __restrict__ wb) {
    __shared__ float s[NK][CIN*9];
    int co = blockIdx.x, b = blockIdx.y;
    for (int idx = threadIdx.x; idx < NK*CIN*9; idx += 256) {
        int k = idx / (CIN*9);
        int jj = idx - k * (CIN*9);
        s[k][jj] = wb[((size_t)k*COUT + co)*(CIN*9) + jj];
    }
    float a0 = g_a[b*NK+0], a1 = g_a[b*NK+1], a2 = g_a[b*NK+2], a3 = g_a[b*NK+3];
    int ct = co >> 6, co_t = (co >> 4) & 3, r = co & 15;
    __syncthreads();
    for (int idx = threadIdx.x; idx < 9*CIN; idx += 256) {
        int tap = idx >> 8;
        int ci  = idx & 255;
        int src = ci*9 + tap;
        float v = a0*s[0][src] + a1*s[1][src] + a2*s[2][src] + a3*s[3][src];
        int stage = ci >> 5, k_t = (ci >> 3) & 3, cc = ci & 7;
        int lane = (r & 7)*4 + (cc & 3);
        int vv   = ((r >> 3) & 1) + 2*((cc >> 2) & 1);
        size_t dst = ((((((((size_t)b*9 + tap)*4 + ct)*8 + stage)*4 + co_t)*4 + k_t)*32 + lane)*4) + vv;
        g_wa[dst] = __uint_as_float(f2tf32(v));
    }
}

// ===================== 4) conv: tf32 mma.sync implicit GEMM =====================
// grid (14 row-quads, 4 co-quarters, 32 b), 128 threads (4 warps), 2 CTAs/SM.
// Block tile: 64 co x (4 rows x 56). Warp tile: 64 co x 56 px (4 m16 x 7 n8).
// One __syncthreads per tap: issue A(g+1) -> compute(g) -> wait -> sync.

#define SX_FLOATS (6*58*PADW)               // 13920
#define SA_FLOATS (4*4*32*4)                // 2048 per buffer (8KB)
#define SMEM_SZ   ((SX_FLOATS + 2*SA_FLOATS) * 4)   // 72064 B

__global__ void __launch_bounds__(128, 2)
conv_kernel(const float* __restrict__ x, float* __restrict__ out) {
    extern __shared__ float smem[];
    float* sx = smem;                        // [r(6)][iw(58)][ci_perm pad 40]
    float* sA = smem + SX_FLOATS;            // [2][co_t(4)][k_t(4)][lane(32)][4]
    uint32_t sxaddr = smem_u32(sx);
    uint32_t saddrA = smem_u32(sA);

    int tid = threadIdx.x, lane = tid & 31;
    int lane4 = lane & 3, laneq = lane >> 2;
    int nt4 = blockIdx.x, ct = blockIdx.y, b = blockIdx.z;
    int h0 = nt4 * NROWS;
    int orow = tid >> 5;                     // warp = output row 0..3

    float c[4][7][4];
    #pragma unroll
    for (int i = 0; i < 4; i++)
        #pragma unroll
        for (int j = 0; j < 7; j++)
            #pragma unroll
            for (int q = 0; q < 4; q++) c[i][j][q] = 0.f;

    const size_t wa_base = (((size_t)b*9)*4 + ct) * 0;   // (indexing done per-tap below)

    // prologue: prefetch A(g=0) into buf 0
    {
        const float* src = g_wa + ((((size_t)b*9 + 0)*4 + ct)*8 + 0) * (size_t)SA_FLOATS;
        #pragma unroll
        for (int it = 0; it < 4; it++) {
            int u = it*128 + tid;            // 0..511 float4 slots
            CP_ASYNC16(saddrA + (uint32_t)(u*16), src + u*4);
        }
        CP_COMMIT();
    }
    (void)wa_base;

    for (int s = 0; s < NSTG; s++) {
        int ci0 = s * CIC;
        // ---- stage sx: 6 rows x 58 cols x 32 ci (k-interleaved), tf32-converted
        for (int u = tid; u < 6*14*32; u += 128) {
            int r  = u / (14*32);
            int rm = u - r * (14*32);
            int q  = rm >> 5;
            int ci = rm & 31;
            int h  = h0 - 1 + r;
            float4 v = make_float4(0.f, 0.f, 0.f, 0.f);
            if (h >= 0 && h < HH)
                v = *(const float4*)(x + ((size_t)(b*CIN + ci0 + ci)*HH + h)*WWD + q*4);
            int p = (ci & 24) + (ci & 3)*2 + ((ci >> 2) & 1);
            float* d = sx + (r*58 + 1 + q*4)*PADW + p;
            d[0*PADW] = __uint_as_float(f2tf32(v.x));
            d[1*PADW] = __uint_as_float(f2tf32(v.y));
            d[2*PADW] = __uint_as_float(f2tf32(v.z));
            d[3*PADW] = __uint_as_float(f2tf32(v.w));
        }
        for (int u = tid; u < 6*2*32; u += 128) {
            int r  = u >> 6;
            int rm = u & 63;
            int e  = rm >> 5;
            int ci = rm & 31;
            sx[(r*58 + e*57)*PADW + ci] = 0.f;
        }
        CP_WAIT0();          // A(s*9) landed (issued last iteration or prologue)
        __syncthreads();     // sx + A visible to all warps

        for (int t = 0; t < 9; t++) {
            int g = s*9 + t;
            int buf = g & 1;
            // ---- issue prefetch of A(g+1) into other buffer (flight overlaps compute)
            if (g + 1 < NTAP) {
                int gn = g + 1;
                int sn = gn / 9, tn = gn - sn*9;
                const float* src = g_wa + ((((size_t)b*9 + tn)*4 + ct)*8 + sn) * (size_t)SA_FLOATS;
                uint32_t dstb = saddrA + (uint32_t)(((gn & 1) * SA_FLOATS) * 4);
                #pragma unroll
                for (int it = 0; it < 4; it++) {
                    int u = it*128 + tid;
                    CP_ASYNC16(dstb + (uint32_t)(u*16), src + u*4);
                }
                CP_COMMIT();
            }

            // ---- compute tap g on buf
            int dy = t / 3, dx = t - dy * 3;
            uint32_t sxw = sxaddr + (uint32_t)((((orow + dy)*58 + dx) * PADW) * 4);
            uint32_t sAb = saddrA + (uint32_t)((buf * SA_FLOATS) * 4);

            #pragma unroll
            for (int kk = 0; kk < 4; kk++) {
                uint32_t a[4][4];
                #pragma unroll
                for (int mt = 0; mt < 4; mt++)
                    LDSV4(a[mt][0], a[mt][1], a[mt][2], a[mt][3],
                          sAb + (uint32_t)(((mt*4 + kk)*32 + lane)*16));
                #pragma unroll
                for (int nt = 0; nt < 7; nt++) {
                    uint32_t bf[2];
                    int col = nt*8 + laneq;
                    LDSV2(bf[0], bf[1], sxw + (uint32_t)((col*PADW + kk*8 + lane4*2) * 4));
                    mma_tf32(c[0][nt], a[0], bf);
                    mma_tf32(c[1][nt], a[1], bf);
                    mma_tf32(c[2][nt], a[2], bf);
                    mma_tf32(c[3][nt], a[3], bf);
                }
            }

            if (t < 8) {        // stage-end sync handled at top of next stage
                CP_WAIT0();     // A(g+1) landed
                __syncthreads();// visible to all + release overwritten buffer
            }
        }
    }

    // ---- epilogue: float2 stores
    int h = h0 + orow;
    #pragma unroll
    for (int mt = 0; mt < 4; mt++) {
        int co_base = ct*64 + mt*16 + laneq;
        #pragma unroll
        for (int half = 0; half < 2; half++) {
            int co = co_base + half*8;
            float* plane = out + ((size_t)(b*COUT + co)*HH + h)*WWD;
            #pragma unroll
            for (int nt = 0; nt < 7; nt++) {
                int wcol = nt*8 + lane4*2;
                *(float2*)(plane + wcol) = make_float2(c[mt][nt][half*2], c[mt][nt][half*2 + 1]);
            }
        }
    }
}

// ===================== launch =====================
extern "C" void kernel_launch(void* const* d_in, const int* in_sizes, int n_in,
                              void* d_out, int out_size) {
    const float* x    = (const float*)d_in[0];
    const float* wb   = (const float*)d_in[1];
    const float* fc1w = (const float*)d_in[2];
    const float* fc1b = (const float*)d_in[3];
    const float* fc2w = (const float*)d_in[4];
    const float* fc2b = (const float*)d_in[5];
    float* out = (float*)d_out;

    cudaFuncSetAttribute(conv_kernel, cudaFuncAttributeMaxDynamicSharedMemorySize, SMEM_SZ);
    cudaFuncSetAttribute(conv_kernel, cudaFuncAttributePreferredSharedMemoryCarveout,
                         cudaSharedmemCarveoutMaxShared);

    gap_kernel<<<BB*CIN, 256>>>(x);
    router_kernel<<<BB, 64>>>(fc1w, fc1b, fc2w, fc2b);
    mix_kernel<<<dim3(COUT, BB), 256>>>(wb);
    conv_kernel<<<dim3(HH/NROWS, 4, BB), 128, SMEM_SZ>>>(x, out);
}

// round 7
// speedup vs baseline: 3.5723x; 1.0941x over previous
#include <cuda_runtime.h>
#include <cstdint>

#define BB   32
#define CIN  256
#define HH   56
#define WWD  56
#define COUT 256
#define NK   4
#define HID  64

#define CIC   32            // ci per stage
#define NSTG  (CIN/CIC)     // 8
#define PADW  40            // padded ci-stride in sx
#define NROWS 4             // output rows per CTA
#define NTAP  72            // NSTG*9 global tap steps

// -------- scratch (device globals) --------
__device__ float g_v[BB*CIN];
__device__ float g_a[BB*NK];
// mixed weights (tf32), fragment-permuted:
// [b][tap][ct(4)][stage(8)][co_t(4)][k_t(4)][lane(32)][v(4)]
__device__ __align__(16) float g_wa[(size_t)BB*9*COUT*CIN];

// ===================== helpers =====================
__device__ __forceinline__ uint32_t smem_u32(const void* p) {
    uint32_t a;
    asm("{ .reg .u64 t; cvta.to.shared.u64 t, %1; cvt.u32.u64 %0, t; }" : "=r"(a) : "l"(p));
    return a;
}
__device__ __forceinline__ uint32_t f2tf32(float f) {
    uint32_t r;
    asm("cvt.rna.tf32.f32 %0, %1;" : "=r"(r) : "f"(f));
    return r;
}
__device__ __forceinline__ void mma_tf32(float* c, const uint32_t* a, const uint32_t* b) {
    asm volatile("mma.sync.aligned.m16n8k8.row.col.f32.tf32.tf32.f32 "
        "{%0,%1,%2,%3}, {%4,%5,%6,%7}, {%8,%9}, {%0,%1,%2,%3};"
        : "+f"(c[0]), "+f"(c[1]), "+f"(c[2]), "+f"(c[3])
        : "r"(a[0]), "r"(a[1]), "r"(a[2]), "r"(a[3]), "r"(b[0]), "r"(b[1]));
}
#define CP_ASYNC16(dst, src) \
    asm volatile("cp.async.ca.shared.global [%0], [%1], 16;" :: "r"(dst), "l"(src) : "memory")
#define CP_COMMIT() asm volatile("cp.async.commit_group;" ::: "memory")
#define CP_WAIT0()  asm volatile("cp.async.wait_group 0;" ::: "memory")

#define LDSV4(r0,r1,r2,r3,a) \
    asm volatile("ld.shared.v4.u32 {%0,%1,%2,%3}, [%4];" : "=r"(r0),"=r"(r1),"=r"(r2),"=r"(r3) : "r"(a))
#define LDSV2(r0,r1,a) \
    asm volatile("ld.shared.v2.u32 {%0,%1}, [%2];" : "=r"(r0),"=r"(r1) : "r"(a))

// ===================== 1) global average pool =====================
__global__ void gap_kernel(const float* __restrict__ x) {
    int bc = blockIdx.x;
    const float* p = x + (size_t)bc * (HH*WWD);
    float s = 0.f;
    for (int i = threadIdx.x; i < HH*WWD; i += 256) s += p[i];
    __shared__ float red[256];
    red[threadIdx.x] = s;
    __syncthreads();
    for (int off = 128; off > 0; off >>= 1) {
        if (threadIdx.x < off) red[threadIdx.x] += red[threadIdx.x + off];
        __syncthreads();
    }
    if (threadIdx.x == 0) g_v[bc] = red[0] * (1.0f / (HH*WWD));
}

// ===================== 2) router MLP + softmax =====================
__global__ void router_kernel(const float* __restrict__ fc1w, const float* __restrict__ fc1b,
                              const float* __restrict__ fc2w, const float* __restrict__ fc2b) {
    int b = blockIdx.x;
    __shared__ float sv[CIN];
    __shared__ float sh[HID];
    __shared__ float sl[NK];
    for (int i = threadIdx.x; i < CIN; i += 64) sv[i] = g_v[b*CIN + i];
    __syncthreads();
    int j = threadIdx.x;
    float acc = fc1b[j];
    for (int c = 0; c < CIN; c++) acc += sv[c] * fc1w[j*CIN + c];
    sh[j] = acc > 0.f ? acc : 0.f;
    __syncthreads();
    if (j < NK) {
        float l = fc2b[j];
        for (int t = 0; t < HID; t++) l += sh[t] * fc2w[j*HID + t];
        sl[j] = l;
    }
    __syncthreads();
    if (j == 0) {
        float m = sl[0];
        for (int k = 1; k < NK; k++) m = fmaxf(m, sl[k]);
        float e[NK], ssum = 0.f;
        for (int k = 0; k < NK; k++) { e[k] = expf(sl[k] - m); ssum += e[k]; }
        float inv = 1.0f / ssum;
        for (int k = 0; k < NK; k++) g_a[b*NK + k] = e[k] * inv;
    }
}

// ===================== 3) mix banks -> fragment-permuted g_wa (tf32) =====================
__global__ void mix_kernel(const float* __restrict__ wb) {
    __shared__ float s[NK][CIN*9];
    int co = blockIdx.x, b = blockIdx.y;
    for (int idx = threadIdx.x; idx < NK*CIN*9; idx += 256) {
        int k = idx / (CIN*9);
        int jj = idx - k * (CIN*9);
        s[k][jj] = wb[((size_t)k*COUT + co)*(CIN*9) + jj];
    }
    float a0 = g_a[b*NK+0], a1 = g_a[b*NK+1], a2 = g_a[b*NK+2], a3 = g_a[b*NK+3];
    int ct = co >> 6, co_t = (co >> 4) & 3, r = co & 15;
    __syncthreads();
    for (int idx = threadIdx.x; idx < 9*CIN; idx += 256) {
        int tap = idx >> 8;
        int ci  = idx & 255;
        int src = ci*9 + tap;
        float v = a0*s[0][src] + a1*s[1][src] + a2*s[2][src] + a3*s[3][src];
        int stage = ci >> 5, k_t = (ci >> 3) & 3, cc = ci & 7;
        int lane = (r & 7)*4 + (cc & 3);
        int vv   = ((r >> 3) & 1) + 2*((cc >> 2) & 1);
        size_t dst = ((((((((size_t)b*9 + tap)*4 + ct)*8 + stage)*4 + co_t)*4 + k_t)*32 + lane)*4) + vv;
        g_wa[dst] = __uint_as_float(f2tf32(v));
    }
}

// ===================== 4) conv: tf32 mma.sync implicit GEMM =====================
// grid (14 row-quads, 4 co-quarters, 32 b), 128 threads (4 warps), 3 CTAs/SM.
// Block tile: 64 co x (4 rows x 56). Warp tile: 64 co x 56 px (4 m16 x 7 n8).
// One __syncthreads per tap: issue A(g+1) -> compute(g) -> wait -> sync.

#define SX_FLOATS (6*58*PADW)               // 13920
#define SA_FLOATS (4*4*32*4)                // 2048 per buffer (8KB)
#define SMEM_SZ   ((SX_FLOATS + 2*SA_FLOATS) * 4)   // 72064 B

__global__ void __launch_bounds__(128, 3)
conv_kernel(const float* __restrict__ x, float* __restrict__ out) {
    extern __shared__ float smem[];
    float* sx = smem;                        // [r(6)][iw(58)][ci_perm pad 40]
    float* sA = smem + SX_FLOATS;            // [2][co_t(4)][k_t(4)][lane(32)][4]
    uint32_t sxaddr = smem_u32(sx);
    uint32_t saddrA = smem_u32(sA);

    int tid = threadIdx.x, lane = tid & 31;
    int lane4 = lane & 3, laneq = lane >> 2;
    int nt4 = blockIdx.x, ct = blockIdx.y, b = blockIdx.z;
    int h0 = nt4 * NROWS;
    int orow = tid >> 5;                     // warp = output row 0..3

    // hoisted per-thread fragment bases (immediate offsets in inner loop)
    uint32_t aLane = saddrA + (uint32_t)(lane * 16);
    uint32_t bLane = (uint32_t)((laneq * PADW + lane4 * 2) * 4);

    float c[4][7][4];
    #pragma unroll
    for (int i = 0; i < 4; i++)
        #pragma unroll
        for (int j = 0; j < 7; j++)
            #pragma unroll
            for (int q = 0; q < 4; q++) c[i][j][q] = 0.f;

    // prologue: prefetch A(g=0) into buf 0
    {
        const float* src = g_wa + ((((size_t)b*9 + 0)*4 + ct)*8 + 0) * (size_t)SA_FLOATS;
        #pragma unroll
        for (int it = 0; it < 4; it++) {
            int u = it*128 + tid;            // 0..511 float4 slots
            CP_ASYNC16(saddrA + (uint32_t)(u*16), src + u*4);
        }
        CP_COMMIT();
    }

    for (int s = 0; s < NSTG; s++) {
        int ci0 = s * CIC;
        // ---- stage sx: 6 rows x 58 cols x 32 ci (k-interleaved), tf32-converted
        for (int u = tid; u < 6*14*32; u += 128) {
            int r  = u / (14*32);
            int rm = u - r * (14*32);
            int q  = rm >> 5;
            int ci = rm & 31;
            int h  = h0 - 1 + r;
            float4 v = make_float4(0.f, 0.f, 0.f, 0.f);
            if (h >= 0 && h < HH)
                v = *(const float4*)(x + ((size_t)(b*CIN + ci0 + ci)*HH + h)*WWD + q*4);
            int p = (ci & 24) + (ci & 3)*2 + ((ci >> 2) & 1);
            float* d = sx + (r*58 + 1 + q*4)*PADW + p;
            d[0*PADW] = __uint_as_float(f2tf32(v.x));
            d[1*PADW] = __uint_as_float(f2tf32(v.y));
            d[2*PADW] = __uint_as_float(f2tf32(v.z));
            d[3*PADW] = __uint_as_float(f2tf32(v.w));
        }
        for (int u = tid; u < 6*2*32; u += 128) {
            int r  = u >> 6;
            int rm = u & 63;
            int e  = rm >> 5;
            int ci = rm & 31;
            sx[(r*58 + e*57)*PADW + ci] = 0.f;
        }
        CP_WAIT0();          // A(s*9) landed (issued last iteration or prologue)
        __syncthreads();     // sx + A visible to all warps

        for (int t = 0; t < 9; t++) {
            int g = s*9 + t;
            int buf = g & 1;
            // ---- issue prefetch of A(g+1) into other buffer (flight overlaps compute)
            if (g + 1 < NTAP) {
                int gn = g + 1;
                int sn = gn / 9, tn = gn - sn*9;
                const float* src = g_wa + ((((size_t)b*9 + tn)*4 + ct)*8 + sn) * (size_t)SA_FLOATS;
                uint32_t dstb = saddrA + (uint32_t)(((gn & 1) * SA_FLOATS) * 4);
                #pragma unroll
                for (int it = 0; it < 4; it++) {
                    int u = it*128 + tid;
                    CP_ASYNC16(dstb + (uint32_t)(u*16), src + u*4);
                }
                CP_COMMIT();
            }

            // ---- compute tap g on buf
            int dy = t / 3, dx = t - dy * 3;
            uint32_t sxw = sxaddr + (uint32_t)((((orow + dy)*58 + dx) * PADW) * 4) + bLane;
            uint32_t sAb = aLane + (uint32_t)((buf * SA_FLOATS) * 4);

            #pragma unroll
            for (int kk = 0; kk < 4; kk++) {
                uint32_t a[4][4];
                #pragma unroll
                for (int mt = 0; mt < 4; mt++)
                    LDSV4(a[mt][0], a[mt][1], a[mt][2], a[mt][3],
                          sAb + (uint32_t)((mt*4 + kk)*512));
                #pragma unroll
                for (int nt = 0; nt < 7; nt++) {
                    uint32_t bf[2];
                    LDSV2(bf[0], bf[1], sxw + (uint32_t)(nt*8*PADW*4 + kk*32));
                    mma_tf32(c[0][nt], a[0], bf);
                    mma_tf32(c[1][nt], a[1], bf);
                    mma_tf32(c[2][nt], a[2], bf);
                    mma_tf32(c[3][nt], a[3], bf);
                }
            }

            if (t < 8) {        // stage-end sync handled at top of next stage
                CP_WAIT0();     // A(g+1) landed
                __syncthreads();// visible to all + release overwritten buffer
            }
        }
    }

    // ---- epilogue: float2 stores
    int h = h0 + orow;
    #pragma unroll
    for (int mt = 0; mt < 4; mt++) {
        int co_base = ct*64 + mt*16 + laneq;
        #pragma unroll
        for (int half = 0; half < 2; half++) {
            int co = co_base + half*8;
            float* plane = out + ((size_t)(b*COUT + co)*HH + h)*WWD;
            #pragma unroll
            for (int nt = 0; nt < 7; nt++) {
                int wcol = nt*8 + lane4*2;
                *(float2*)(plane + wcol) = make_float2(c[mt][nt][half*2], c[mt][nt][half*2 + 1]);
            }
        }
    }
}

// ===================== launch =====================
extern "C" void kernel_launch(void* const* d_in, const int* in_sizes, int n_in,
                              void* d_out, int out_size) {
    const float* x    = (const float*)d_in[0];
    const float* wb   = (const float*)d_in[1];
    const float* fc1w = (const float*)d_in[2];
    const float* fc1b = (const float*)d_in[3];
    const float* fc2w = (const float*)d_in[4];
    const float* fc2b = (const float*)d_in[5];
    float* out = (float*)d_out;

    cudaFuncSetAttribute(conv_kernel, cudaFuncAttributeMaxDynamicSharedMemorySize, SMEM_SZ);
    cudaFuncSetAttribute(conv_kernel, cudaFuncAttributePreferredSharedMemoryCarveout,
                         cudaSharedmemCarveoutMaxShared);

    gap_kernel<<<BB*CIN, 256>>>(x);
    router_kernel<<<BB, 64>>>(fc1w, fc1b, fc2w, fc2b);
    mix_kernel<<<dim3(COUT, BB), 256>>>(wb);
    conv_kernel<<<dim3(HH/NROWS, 4, BB), 128, SMEM_SZ>>>(x, out);
}